// round 3
// baseline (speedup 1.0000x reference)
#include <cuda_runtime.h>
#include <math.h>

#define NBATCH 8
#define DPIX   147456       // 384*384
#define KB     128          // fine-grid bins
#define BINS   50
#define B_ROW  130          // odd-parity array row stride (even -> 8B align w/ +1)
#define B_TOT  (NBATCH*KB*B_ROW + 4)

// Scratch. __device__ globals are zero-initialized at module load; the
// histogram arrays are returned to all-zero by k_stageC on every call,
// so no explicit zero-fill kernel is needed.
__device__ __align__(16) float g_A[NBATCH * KB * KB];   // even-j0 histogram (512 KB)
__device__ __align__(16) float g_Braw[B_TOT];           // odd-j0 histogram (+1 float offset)
__device__ __align__(16) float g_G [BINS * KB];         // G[b][i]
__device__ __align__(16) float g_GT[KB * BINS];         // GT[i][b]
__device__ __align__(16) float g_P [4 * NBATCH * BINS * KB]; // P partials [ic][n][b][j]
__device__ __align__(16) float g_hgram[NBATCH * BINS * BINS];

// ---------------- Kernel 1: histogram (bilinear, vector REDs) + G table -------
__device__ __forceinline__ void red2(float* p, float a, float b) {
    asm volatile("red.global.add.v2.f32 [%0], {%1, %2};"
                 :: "l"(p), "f"(a), "f"(b) : "memory");
}

__global__ void k_hist(const float* __restrict__ im1, const float* __restrict__ im2) {
    int gid = blockIdx.x * blockDim.x + threadIdx.x;   // one float4 chunk (4 pixels)

    // fold G-table computation into the first BINS*KB threads
    if (gid < BINS * KB) {
        int b = gid / KB, i = gid % KB;
        float x = (i + 0.5f) * (1.0f / KB);
        float c = (b + 0.5f) * 0.02f;
        float d = 10.0f * (x - c);
        float s1 = 1.0f / (1.0f + expf(-(d + 0.1f)));
        float s2 = 1.0f / (1.0f + expf(-(d - 0.1f)));
        float v = s1 - s2;
        g_G [b * KB  + i] = v;
        g_GT[i * BINS + b] = v;
    }

    const int nchunk = (NBATCH * DPIX) / 4;
    if (gid >= nchunk) return;
    int n = gid / (DPIX / 4);                  // 36864 chunks per batch, no straddle
    float4 xv = ((const float4*)im1)[gid];
    float4 yv = ((const float4*)im2)[gid];
    size_t baseA = (size_t)n * KB * KB;
    size_t baseB = (size_t)n * KB * B_ROW;

    float xs[4] = {xv.x, xv.y, xv.z, xv.w};
    float ys[4] = {yv.x, yv.y, yv.z, yv.w};
#pragma unroll
    for (int q = 0; q < 4; q++) {
        float u = xs[q] * (float)KB - 0.5f;
        float fi = fminf((float)(KB - 2), fmaxf(0.0f, floorf(u)));
        int   i0 = (int)fi;
        float wx = u - fi;
        float v  = ys[q] * (float)KB - 0.5f;
        float fj = fminf((float)(KB - 2), fmaxf(0.0f, floorf(v)));
        int   j0 = (int)fj;
        float wy = v - fj;
        float ax = 1.0f - wx, ay = 1.0f - wy;

        bool odd = (j0 & 1);
        float* arr = odd ? (g_Braw + 1 + baseB) : (g_A + baseA);
        int    rs  = odd ? B_ROW : KB;
        float* p   = arr + (size_t)i0 * rs + j0;     // 8B-aligned by parity
        red2(p,      ax * ay, ax * wy);
        red2(p + rs, wx * ay, wx * wy);
    }
}

// ---------------- Kernel 2: P[ic][n][b][j] = sum_i G[b][i]*H[n][i][j]; re-zero H
// grid = 8(n) * 4(i-chunk of 32) = 32 blocks, 128 threads (j)
__global__ void __launch_bounds__(128) k_stageC() {
    int n  = blockIdx.x >> 2;
    int ic = blockIdx.x & 3;
    int j  = threadIdx.x;
    int i_beg = ic * 32;

    __shared__ float Gs[32][BINS + 2];   // +2 pad vs bank conflicts (broadcast anyway)
    for (int t = threadIdx.x; t < 32 * BINS; t += 128) {
        int ii = t / BINS, k = t % BINS;
        Gs[ii][k] = g_GT[(i_beg + ii) * BINS + k];
    }
    __syncthreads();

    float acc[BINS];
#pragma unroll
    for (int k = 0; k < BINS; k++) acc[k] = 0.0f;

    float* A = g_A    +     (size_t)n * KB * KB    + (size_t)i_beg * KB    + j;
    float* B = g_Braw + 1 + (size_t)n * KB * B_ROW + (size_t)i_beg * B_ROW + j;

    for (int ii = 0; ii < 32; ii++) {
        float h = A[(size_t)ii * KB] + B[(size_t)ii * B_ROW];
        A[(size_t)ii * KB]    = 0.0f;    // restore all-zero state for next call
        B[(size_t)ii * B_ROW] = 0.0f;
#pragma unroll
        for (int k = 0; k < BINS; k++) acc[k] += h * Gs[ii][k];
    }

    size_t pb = (((size_t)ic * NBATCH + n) * BINS) * KB + j;
#pragma unroll
    for (int k = 0; k < BINS; k++) g_P[pb + (size_t)k * KB] = acc[k];
}

// ---------------- Kernel 3: hgram[nb][c] = sum_j (sum_ic P)[nb][j] * G[c][j] --
// grid = 400 (nb = n*50+b), 64 threads
__global__ void __launch_bounds__(64) k_stageD() {
    int nb = blockIdx.x;
    __shared__ float Ps[KB];
    const int PSTRIDE = NBATCH * BINS * KB;
    const float* P = g_P + (size_t)nb * KB;
#pragma unroll
    for (int t = 0; t < 2; t++) {
        int jj = threadIdx.x + t * 64;
        Ps[jj] = P[jj] + P[jj + PSTRIDE] + P[jj + 2 * PSTRIDE] + P[jj + 3 * PSTRIDE];
    }
    __syncthreads();

    int c = threadIdx.x;
    if (c < BINS) {
        const float* Gc = g_G + (size_t)c * KB;
        float a0 = 0.f, a1 = 0.f, a2 = 0.f, a3 = 0.f;
#pragma unroll
        for (int q = 0; q < KB; q += 4) {
            a0 += Ps[q]     * __ldg(Gc + q);
            a1 += Ps[q + 1] * __ldg(Gc + q + 1);
            a2 += Ps[q + 2] * __ldg(Gc + q + 2);
            a3 += Ps[q + 3] * __ldg(Gc + q + 3);
        }
        g_hgram[(size_t)nb * BINS + c] = (a0 + a1) + (a2 + a3);
    }
}

// ---------------- Kernel 4: normalize, marginals, MI --------------------------
__global__ void k_stageE(float* __restrict__ out) {
    __shared__ float red[512];
    __shared__ float mx[NBATCH * BINS], my[NBATCH * BINS];
    __shared__ float sS;
    int tid = threadIdx.x;
    const int TOT = NBATCH * BINS * BINS;

    float s = 0.0f;
    for (int t = tid; t < TOT; t += 512) s += g_hgram[t];
    red[tid] = s; __syncthreads();
    for (int o = 256; o; o >>= 1) { if (tid < o) red[tid] += red[tid + o]; __syncthreads(); }
    if (tid == 0) sS = red[0];

    if (tid < NBATCH * BINS) {
        int n = tid / BINS, b = tid % BINS;
        const float* Hn = g_hgram + (size_t)n * BINS * BINS;
        float m1 = 0.0f, m2 = 0.0f;
        for (int c = 0; c < BINS; c++) { m1 += Hn[b * BINS + c]; m2 += Hn[c * BINS + b]; }
        mx[tid] = m1; my[tid] = m2;
    }
    __syncthreads();

    float inv = 1.0f / sS;
    float mi = 0.0f;
    for (int t = tid; t < TOT; t += 512) {
        int n = t / (BINS * BINS);
        int rem = t - n * (BINS * BINS);
        int b = rem / BINS, c = rem % BINS;
        float p = g_hgram[t] * inv;
        float q = (mx[n * BINS + b] * inv) * (my[n * BINS + c] * inv);
        mi += p * (logf(p + 1e-8f) - logf(q + 1e-8f));
    }
    red[tid] = mi; __syncthreads();
    for (int o = 256; o; o >>= 1) { if (tid < o) red[tid] += red[tid + o]; __syncthreads(); }
    if (tid == 0) out[0] = red[0];
}

// ---------------- Launch -------------------------------------------------------
extern "C" void kernel_launch(void* const* d_in, const int* in_sizes, int n_in,
                              void* d_out, int out_size) {
    const float* im1 = (const float*)d_in[0];
    const float* im2 = (const float*)d_in[1];
    k_hist  <<<(NBATCH * DPIX / 4 + 255) / 256, 256>>>(im1, im2);
    k_stageC<<<32, 128>>>();
    k_stageD<<<400, 64>>>();
    k_stageE<<<1, 512>>>((float*)d_out);
}